// round 5
// baseline (speedup 1.0000x reference)
#include <cuda_runtime.h>
#include <math.h>

#define NB 8
#define NT 256
#define NDI 64
#define ND 128
#define NROWS (NB*NT)
#define NOUT 672

__device__ float g_f[NROWS*ND];
__device__ float g_k[NROWS*ND];
__device__ float g_v[NROWS*ND];
__device__ float g_theta[NROWS];
__device__ float g_eta[NROWS];
__device__ float g_alpha[NROWS];
__device__ float g_qlast[NB*ND];
__device__ float g_mlast[NB*ND];
__device__ float g_G[NB*NT*NT];     // G[b][t][tau]
__device__ float g_W[NB*NT*NT];     // TRANSPOSED: Wt[b][tau][t]
__device__ float g_Gq[NB*NT];
__device__ float g_mcoef[NB*NT];
__device__ int   g_ctr[16];

__device__ __forceinline__ float gelu_t(float x) {
    float x3 = x*x*x;
    return 0.5f*x*(1.0f + tanhf(0.79788456080286535588f*(x + 0.044715f*x3)));
}
__device__ __forceinline__ float sigmoid_f(float x) {
    return 1.0f/(1.0f + expf(-x));
}

// =====================================================================
// Launch 1: f = gelu(x @ W_b + b_b) + counter reset
// =====================================================================
__global__ __launch_bounds__(256) void fgemm_kernel(
    const float* __restrict__ A, const float* __restrict__ Bm,
    const float* __restrict__ bias)
{
    if (blockIdx.x == 0 && blockIdx.y == 0 && threadIdx.x < 16)
        g_ctr[threadIdx.x] = 0;

    __shared__ float As[16][64];
    __shared__ float Bs[16][64];
    int tid = threadIdx.x;
    int bm = blockIdx.x * 64, bn = blockIdx.y * 64;
    int ar = tid >> 2, ac = (tid & 3) * 4;
    int br = tid >> 4, bc = (tid & 15) * 4;
    int rm = (tid >> 4) * 4, rn = (tid & 15) * 4;

    float acc[4][4];
#pragma unroll
    for (int i = 0; i < 4; ++i)
#pragma unroll
        for (int j = 0; j < 4; ++j) acc[i][j] = 0.0f;

    for (int k0 = 0; k0 < NDI; k0 += 16) {
        float4 a = *(const float4*)(A + (size_t)(bm + ar) * NDI + k0 + ac);
        As[ac+0][ar]=a.x; As[ac+1][ar]=a.y; As[ac+2][ar]=a.z; As[ac+3][ar]=a.w;
        *(float4*)(&Bs[br][bc]) =
            *(const float4*)(Bm + (size_t)(k0 + br) * ND + bn + bc);
        __syncthreads();
#pragma unroll
        for (int kk = 0; kk < 16; ++kk) {
            float4 av = *(const float4*)(&As[kk][rm]);
            float4 bv = *(const float4*)(&Bs[kk][rn]);
            acc[0][0]=fmaf(av.x,bv.x,acc[0][0]); acc[0][1]=fmaf(av.x,bv.y,acc[0][1]);
            acc[0][2]=fmaf(av.x,bv.z,acc[0][2]); acc[0][3]=fmaf(av.x,bv.w,acc[0][3]);
            acc[1][0]=fmaf(av.y,bv.x,acc[1][0]); acc[1][1]=fmaf(av.y,bv.y,acc[1][1]);
            acc[1][2]=fmaf(av.y,bv.z,acc[1][2]); acc[1][3]=fmaf(av.y,bv.w,acc[1][3]);
            acc[2][0]=fmaf(av.z,bv.x,acc[2][0]); acc[2][1]=fmaf(av.z,bv.y,acc[2][1]);
            acc[2][2]=fmaf(av.z,bv.z,acc[2][2]); acc[2][3]=fmaf(av.z,bv.w,acc[2][3]);
            acc[3][0]=fmaf(av.w,bv.x,acc[3][0]); acc[3][1]=fmaf(av.w,bv.y,acc[3][1]);
            acc[3][2]=fmaf(av.w,bv.z,acc[3][2]); acc[3][3]=fmaf(av.w,bv.w,acc[3][3]);
        }
        __syncthreads();
    }
    float4 bb;
    bb.x=bias[bn+rn+0]; bb.y=bias[bn+rn+1]; bb.z=bias[bn+rn+2]; bb.w=bias[bn+rn+3];
#pragma unroll
    for (int i = 0; i < 4; ++i) {
        float4 o;
        o.x=gelu_t(acc[i][0]+bb.x); o.y=gelu_t(acc[i][1]+bb.y);
        o.z=gelu_t(acc[i][2]+bb.z); o.w=gelu_t(acc[i][3]+bb.w);
        *(float4*)(g_f + (size_t)(bm+rm+i) * ND + bn + rn) = o;
    }
}

// =====================================================================
// Launch 2: mega — k/v GEMM [0,128) + meta [128,384) + qlast [384,392)
// =====================================================================
__global__ __launch_bounds__(256) void mega_kernel(
    const float* __restrict__ Wk, const float* __restrict__ Wv,
    const float* __restrict__ Wq,
    const float* __restrict__ Wm, const float* __restrict__ bm_)
{
    __shared__ float smem_u[2 * 16 * 64];
    int idx = blockIdx.x, tid = threadIdx.x;

    if (idx < 128) {
        float (*As)[64] = (float(*)[64])smem_u;
        float (*Bs)[64] = (float(*)[64])(smem_u + 16 * 64);
        const float* Bm = (idx >> 6) ? Wv : Wk;
        float* C = (idx >> 6) ? g_v : g_k;
        int bm = (idx & 31) * 64, bn = ((idx >> 5) & 1) * 64;
        int ar = tid >> 2, ac = (tid & 3) * 4;
        int br = tid >> 4, bc = (tid & 15) * 4;
        int rm = (tid >> 4) * 4, rn = (tid & 15) * 4;

        float acc[4][4];
#pragma unroll
        for (int i = 0; i < 4; ++i)
#pragma unroll
            for (int j = 0; j < 4; ++j) acc[i][j] = 0.0f;

        for (int k0 = 0; k0 < ND; k0 += 16) {
            float4 a = *(const float4*)(g_f + (size_t)(bm + ar) * ND + k0 + ac);
            As[ac+0][ar]=a.x; As[ac+1][ar]=a.y; As[ac+2][ar]=a.z; As[ac+3][ar]=a.w;
            *(float4*)(&Bs[br][bc]) =
                *(const float4*)(Bm + (size_t)(k0 + br) * ND + bn + bc);
            __syncthreads();
#pragma unroll
            for (int kk = 0; kk < 16; ++kk) {
                float4 av = *(const float4*)(&As[kk][rm]);
                float4 bv = *(const float4*)(&Bs[kk][rn]);
                acc[0][0]=fmaf(av.x,bv.x,acc[0][0]); acc[0][1]=fmaf(av.x,bv.y,acc[0][1]);
                acc[0][2]=fmaf(av.x,bv.z,acc[0][2]); acc[0][3]=fmaf(av.x,bv.w,acc[0][3]);
                acc[1][0]=fmaf(av.y,bv.x,acc[1][0]); acc[1][1]=fmaf(av.y,bv.y,acc[1][1]);
                acc[1][2]=fmaf(av.y,bv.z,acc[1][2]); acc[1][3]=fmaf(av.y,bv.w,acc[1][3]);
                acc[2][0]=fmaf(av.z,bv.x,acc[2][0]); acc[2][1]=fmaf(av.z,bv.y,acc[2][1]);
                acc[2][2]=fmaf(av.z,bv.z,acc[2][2]); acc[2][3]=fmaf(av.z,bv.w,acc[2][3]);
                acc[3][0]=fmaf(av.w,bv.x,acc[3][0]); acc[3][1]=fmaf(av.w,bv.y,acc[3][1]);
                acc[3][2]=fmaf(av.w,bv.z,acc[3][2]); acc[3][3]=fmaf(av.w,bv.w,acc[3][3]);
            }
            __syncthreads();
        }
#pragma unroll
        for (int i = 0; i < 4; ++i) {
            float4 o; o.x=acc[i][0]; o.y=acc[i][1]; o.z=acc[i][2]; o.w=acc[i][3];
            *(float4*)(C + (size_t)(bm+rm+i) * ND + bn + rn) = o;
        }
    } else if (idx < 384) {
        int warp = tid >> 5, lane = tid & 31;
        int row = (idx - 128) * 8 + warp;
        const float4* f4 = (const float4*)g_f + (size_t)row * 32;
        float4 fv = f4[lane];
        const float* wp = Wm + lane * 12;
        float d0 = fv.x*wp[0] + fv.y*wp[3] + fv.z*wp[6] + fv.w*wp[9];
        float d1 = fv.x*wp[1] + fv.y*wp[4] + fv.z*wp[7] + fv.w*wp[10];
        float d2 = fv.x*wp[2] + fv.y*wp[5] + fv.z*wp[8] + fv.w*wp[11];
#pragma unroll
        for (int o = 16; o > 0; o >>= 1) {
            d0 += __shfl_xor_sync(0xffffffffu, d0, o);
            d1 += __shfl_xor_sync(0xffffffffu, d1, o);
            d2 += __shfl_xor_sync(0xffffffffu, d2, o);
        }
        if (lane == 0) {
            g_theta[row] = 0.01f * sigmoid_f(d0 + bm_[0]);
            g_eta[row]   =         sigmoid_f(d1 + bm_[1]);
            g_alpha[row] = 0.1f  * sigmoid_f(d2 + bm_[2]);
        }
    } else {
        int b = idx - 384;
        float* fl = smem_u;
        float* part = smem_u + 128;
        if (tid < ND) fl[tid] = g_f[(size_t)(b * NT + NT - 1) * ND + tid];
        __syncthreads();
        int j = tid & 127, h = tid >> 7;
        float acc = 0.f;
        int i0 = h * 64;
#pragma unroll 16
        for (int i = 0; i < 64; ++i)
            acc = fmaf(fl[i0 + i], Wq[(size_t)(i0 + i) * ND + j], acc);
        part[tid] = acc;
        __syncthreads();
        if (tid < ND) g_qlast[b * ND + j] = part[tid] + part[tid + 128];
    }
}

// =====================================================================
// Launch 3: per batch — G = K K^T (16 tiles) + Gq (1 block); last CTA
// builds TRANSPOSED Wt via smem-staged transpose (coalesced both ways).
// =====================================================================
__global__ __launch_bounds__(256) void gprep_kernel()
{
    __shared__ float smem_u[2 * 16 * 64];
    __shared__ float eta_s[NT];
    __shared__ float r_s[NT];
    __shared__ float qsm[ND];
    __shared__ float gbuf[16 * 256];
    __shared__ float wbuf[256 * 17];
    __shared__ int sflag;

    int b = blockIdx.x / 17;
    int r = blockIdx.x % 17;
    int tid = threadIdx.x;
    const float* Kb = g_k + (size_t)b * NT * ND;
    float* Gb = g_G + (size_t)b * NT * NT;

    if (r < 16) {
        float (*As)[64] = (float(*)[64])smem_u;
        float (*Bs)[64] = (float(*)[64])(smem_u + 16 * 64);
        int I = (r >> 2) * 64, J = (r & 3) * 64;
        int ar = tid >> 2, ac = (tid & 3) * 4;
        int rm = (tid >> 4) * 4, rn = (tid & 15) * 4;

        float acc[4][4];
#pragma unroll
        for (int i = 0; i < 4; ++i)
#pragma unroll
            for (int j = 0; j < 4; ++j) acc[i][j] = 0.0f;

        for (int k0 = 0; k0 < ND; k0 += 16) {
            float4 a = *(const float4*)(Kb + (size_t)(I + ar) * ND + k0 + ac);
            As[ac+0][ar]=a.x; As[ac+1][ar]=a.y; As[ac+2][ar]=a.z; As[ac+3][ar]=a.w;
            float4 bvec = *(const float4*)(Kb + (size_t)(J + ar) * ND + k0 + ac);
            Bs[ac+0][ar]=bvec.x; Bs[ac+1][ar]=bvec.y; Bs[ac+2][ar]=bvec.z; Bs[ac+3][ar]=bvec.w;
            __syncthreads();
#pragma unroll
            for (int kk = 0; kk < 16; ++kk) {
                float4 av = *(const float4*)(&As[kk][rm]);
                float4 bv = *(const float4*)(&Bs[kk][rn]);
                acc[0][0]=fmaf(av.x,bv.x,acc[0][0]); acc[0][1]=fmaf(av.x,bv.y,acc[0][1]);
                acc[0][2]=fmaf(av.x,bv.z,acc[0][2]); acc[0][3]=fmaf(av.x,bv.w,acc[0][3]);
                acc[1][0]=fmaf(av.y,bv.x,acc[1][0]); acc[1][1]=fmaf(av.y,bv.y,acc[1][1]);
                acc[1][2]=fmaf(av.y,bv.z,acc[1][2]); acc[1][3]=fmaf(av.y,bv.w,acc[1][3]);
                acc[2][0]=fmaf(av.z,bv.x,acc[2][0]); acc[2][1]=fmaf(av.z,bv.y,acc[2][1]);
                acc[2][2]=fmaf(av.z,bv.z,acc[2][2]); acc[2][3]=fmaf(av.z,bv.w,acc[2][3]);
                acc[3][0]=fmaf(av.w,bv.x,acc[3][0]); acc[3][1]=fmaf(av.w,bv.y,acc[3][1]);
                acc[3][2]=fmaf(av.w,bv.z,acc[3][2]); acc[3][3]=fmaf(av.w,bv.w,acc[3][3]);
            }
            __syncthreads();
        }
#pragma unroll
        for (int i = 0; i < 4; ++i) {
            float4 o; o.x=acc[i][0]; o.y=acc[i][1]; o.z=acc[i][2]; o.w=acc[i][3];
            *(float4*)(Gb + (size_t)(I+rm+i) * NT + J + rn) = o;
        }
    } else {
        if (tid < ND) qsm[tid] = g_qlast[b * ND + tid];
        __syncthreads();
        const float* krow = Kb + (size_t)tid * ND;
        float acc = 0.f;
#pragma unroll 8
        for (int d = 0; d < ND; ++d) acc = fmaf(krow[d], qsm[d], acc);
        g_Gq[b * NT + tid] = acc;
    }

    __threadfence();
    __syncthreads();
    if (tid == 0) sflag = atomicAdd(&g_ctr[8 + b], 1);
    __syncthreads();
    if (sflag != 16) return;
    __threadfence();

    // ---- W-prep tail: Wt[tau][t] = -th_tau * G[t][tau] * h_tau(t-1) ----
    int tau = tid;
    eta_s[tid] = g_eta[b * NT + tid];
    r_s[tid]   = 1.0f - g_alpha[b * NT + tid];
    float th   = g_theta[b * NT + tau];
    float gq   = g_Gq[b * NT + tau];
    __syncthreads();

    float* Wtb = g_W + (size_t)b * NT * NT;
    float h = 1.f, pp = 1.f;
    for (int t0 = 0; t0 < NT; t0 += 16) {
        // stage 16 rows of G (coalesced)
#pragma unroll
        for (int rep = 0; rep < 16; ++rep)
            gbuf[rep * 256 + tid] = Gb[(size_t)(t0 + rep) * NT + tid];
        __syncthreads();
        // serial h recurrence over this t-chunk
#pragma unroll
        for (int i2 = 0; i2 < 16; ++i2) {
            int t = t0 + i2;
            float w = 0.f;
            if (tau < t) {
                w = -th * gbuf[i2 * 256 + tau] * h;
                pp *= eta_s[t];
                h = fmaf(r_s[t], h, pp);
            }
            wbuf[tau * 17 + i2] = w;
        }
        __syncthreads();
        // transposed coalesced store: Wt[r][t0+j]
#pragma unroll
        for (int rep = 0; rep < 16; ++rep) {
            int idx = rep * 256 + tid;
            int rr = idx >> 4;
            int j = idx & 15;
            Wtb[(size_t)rr * NT + t0 + j] = wbuf[rr * 17 + j];
        }
        __syncthreads();
    }
    g_mcoef[b * NT + tau] = -th * h * gq;
}

// =====================================================================
// Launch 4: solve. 1 warp = 1 row, 32 lanes = 32 slots, 8 chunks of 32.
// Serial phase register-only; dense updates coalesced __ldg, off-chain.
// Grid = 8 batches x 16 row-groups = 128 CTAs x 256 thr.
// =====================================================================
__device__ __forceinline__ void head_body(
    int b, int tid,
    const float* __restrict__ W_f, const float* __restrict__ b_f,
    const float* __restrict__ W1,  const float* __restrict__ b1,
    const float* __restrict__ g1,  const float* __restrict__ be1,
    const float* __restrict__ W2,  const float* __restrict__ b2,
    float* __restrict__ out,
    float* z, float* fused, float* tbuf, float* h)
{
    if (tid < ND)        z[tid] = g_f[(size_t)(b * NT + NT - 1) * ND + tid];
    else if (tid < 2*ND) z[tid] = g_mlast[b * ND + (tid - ND)];
    __syncthreads();
    if (tid < ND) {
        float acc = b_f[tid];
#pragma unroll 8
        for (int i = 0; i < 2 * ND; ++i)
            acc = fmaf(z[i], W_f[(size_t)i * ND + tid], acc);
        float g = sigmoid_f(acc);
        fused[tid] = z[tid] * g + z[ND + tid] * (1.0f - g);
    }
    __syncthreads();
    if (tid < ND) {
        float acc = b1[tid];
#pragma unroll 8
        for (int i = 0; i < ND; ++i)
            acc = fmaf(fused[i], W1[(size_t)i * ND + tid], acc);
        tbuf[tid] = acc;
    }
    __syncthreads();
    float sum = 0.f, sq = 0.f;
#pragma unroll 8
    for (int i = 0; i < ND; ++i) { float t = tbuf[i]; sum += t; sq += t*t; }
    float mu = sum * (1.0f / ND);
    float var = sq * (1.0f / ND) - mu * mu;
    float rstd = rsqrtf(var + 1e-5f);
    if (tid < ND) {
        float ln = (tbuf[tid] - mu) * rstd * g1[tid] + be1[tid];
        h[tid] = gelu_t(ln);
    }
    __syncthreads();
    for (int o = tid; o < NOUT; o += 256) {
        float acc = b2[o];
#pragma unroll 8
        for (int i = 0; i < ND; ++i)
            acc = fmaf(h[i], W2[(size_t)i * NOUT + o], acc);
        out[b * NOUT + o] = acc;
    }
}

template<int C>
__device__ __forceinline__ void chunk_body(
    const float* __restrict__ Wtb, float* rhs, float& macc,
    const float* __restrict__ mcobuf, int u)
{
    // diagonal block into registers (coalesced loads)
    float dreg[32];
#pragma unroll
    for (int tt = 0; tt < 32; ++tt)
        dreg[tt] = __ldg(Wtb + (size_t)(32*C + tt) * NT + 32*C + u);

    // serial intra-chunk solve: registers + shfl only
    float r0 = rhs[0];
#pragma unroll
    for (int tt = 0; tt < 32; ++tt) {
        float E = __shfl_sync(0xffffffffu, r0, tt);
        if (u > tt) r0 = fmaf(dreg[tt], E, r0);
    }
    float cur = r0;
    macc = fmaf(mcobuf[32*C + u], cur, macc);

    // dense rank-32 update of future chunks (coalesced, off-chain)
#pragma unroll
    for (int tt = 0; tt < 32; ++tt) {
        float E = __shfl_sync(0xffffffffu, cur, tt);
        const float* wp = Wtb + (size_t)(32*C + tt) * NT + u;
#pragma unroll
        for (int m = 1; m < 8 - C; ++m)
            rhs[m] = fmaf(__ldg(wp + 32*(C + m)), E, rhs[m]);
    }
    // shift window
#pragma unroll
    for (int m = 0; m < 7; ++m) rhs[m] = rhs[m+1];
}

__global__ __launch_bounds__(256) void solve_head_kernel(
    const float* __restrict__ W_f, const float* __restrict__ b_f,
    const float* __restrict__ W1,  const float* __restrict__ b1,
    const float* __restrict__ g1,  const float* __restrict__ be1,
    const float* __restrict__ W2,  const float* __restrict__ b2,
    float* __restrict__ out)
{
    __shared__ float vbuf[8 * 264];
    __shared__ float mcobuf[NT];
    __shared__ float z[2 * ND];
    __shared__ float fusedv[ND];
    __shared__ float tbuf[ND];
    __shared__ float hh[ND];
    __shared__ int sflag;

    int tid = threadIdx.x;
    int b = blockIdx.x >> 4;
    int g = blockIdx.x & 15;
    int w = tid >> 5;
    int u = tid & 31;
    int i = g * 8 + w;           // row within batch

    // stage v transposed: vbuf[ii][t]
#pragma unroll
    for (int rep = 0; rep < 8; ++rep) {
        int t = rep * 32 + (tid >> 3);
        int ii = tid & 7;
        vbuf[ii * 264 + t] = g_v[(size_t)(b * NT + t) * ND + g * 8 + ii];
    }
    mcobuf[tid] = g_mcoef[b * NT + tid];
    __syncthreads();

    float rhs[8];
#pragma unroll
    for (int m = 0; m < 8; ++m)
        rhs[m] = -vbuf[w * 264 + u + 32 * m];

    const float* Wtb = g_W + (size_t)b * NT * NT;
    float macc = 0.f;

    chunk_body<0>(Wtb, rhs, macc, mcobuf, u);
    chunk_body<1>(Wtb, rhs, macc, mcobuf, u);
    chunk_body<2>(Wtb, rhs, macc, mcobuf, u);
    chunk_body<3>(Wtb, rhs, macc, mcobuf, u);
    chunk_body<4>(Wtb, rhs, macc, mcobuf, u);
    chunk_body<5>(Wtb, rhs, macc, mcobuf, u);
    chunk_body<6>(Wtb, rhs, macc, mcobuf, u);
    chunk_body<7>(Wtb, rhs, macc, mcobuf, u);

    // reduce macc across the warp -> m_last for this row
#pragma unroll
    for (int o = 16; o > 0; o >>= 1)
        macc += __shfl_xor_sync(0xffffffffu, macc, o);
    if (u == 0) g_mlast[b * ND + i] = macc;

    __threadfence();
    __syncthreads();
    if (tid == 0) sflag = atomicAdd(&g_ctr[b], 1);
    __syncthreads();
    if (sflag == 15) {
        __threadfence();
        head_body(b, tid, W_f, b_f, W1, b1, g1, be1, W2, b2, out,
                  z, fusedv, tbuf, hh);
    }
}

// ---------------- launch ----------------------------------------------------
extern "C" void kernel_launch(void* const* d_in, const int* in_sizes, int n_in,
                              void* d_out, int out_size)
{
    const float* x   = (const float*)d_in[0];
    const float* W_b = (const float*)d_in[1];
    const float* b_b = (const float*)d_in[2];
    const float* Wk  = (const float*)d_in[3];
    const float* Wv  = (const float*)d_in[4];
    const float* Wq  = (const float*)d_in[5];
    const float* W_m = (const float*)d_in[6];
    const float* b_m = (const float*)d_in[7];
    const float* W_f = (const float*)d_in[8];
    const float* b_f = (const float*)d_in[9];
    const float* W1  = (const float*)d_in[10];
    const float* b1  = (const float*)d_in[11];
    const float* g1  = (const float*)d_in[12];
    const float* be1 = (const float*)d_in[13];
    const float* W2  = (const float*)d_in[14];
    const float* b2  = (const float*)d_in[15];
    float* out = (float*)d_out;

    fgemm_kernel<<<dim3(32, 2), 256>>>(x, W_b, b_b);
    mega_kernel<<<392, 256>>>(Wk, Wv, Wq, W_m, b_m);
    gprep_kernel<<<NB * 17, 256>>>();
    solve_head_kernel<<<128, 256>>>(W_f, b_f, W1, b1, g1, be1, W2, b2, out);
}

// round 6
// speedup vs baseline: 1.6143x; 1.6143x over previous
#include <cuda_runtime.h>
#include <math.h>

#define NB 8
#define NT 256
#define NDI 64
#define ND 128
#define NROWS (NB*NT)
#define NOUT 672

__device__ float g_f[NROWS*ND];
__device__ float g_k[NROWS*ND];
__device__ float g_v[NROWS*ND];
__device__ float g_theta[NROWS];
__device__ float g_eta[NROWS];
__device__ float g_alpha[NROWS];
__device__ float g_qlast[NB*ND];
__device__ float g_mlast[NB*ND];
__device__ float g_G[NB*NT*NT];     // G[b][t][tau]
__device__ float g_W[NB*NT*NT];     // W[b][t][tau] row-major (strictly lower)
__device__ float g_Gq[NB*NT];
__device__ float g_mcoef[NB*NT];
__device__ int   g_ctr[16];

__device__ __forceinline__ float gelu_t(float x) {
    float x3 = x*x*x;
    return 0.5f*x*(1.0f + tanhf(0.79788456080286535588f*(x + 0.044715f*x3)));
}
__device__ __forceinline__ float sigmoid_f(float x) {
    return 1.0f/(1.0f + expf(-x));
}

// =====================================================================
// Launch 1: f = gelu(x @ W_b + b_b) + counter reset
// =====================================================================
__global__ __launch_bounds__(256) void fgemm_kernel(
    const float* __restrict__ A, const float* __restrict__ Bm,
    const float* __restrict__ bias)
{
    if (blockIdx.x == 0 && blockIdx.y == 0 && threadIdx.x < 16)
        g_ctr[threadIdx.x] = 0;

    __shared__ float As[16][64];
    __shared__ float Bs[16][64];
    int tid = threadIdx.x;
    int bm = blockIdx.x * 64, bn = blockIdx.y * 64;
    int ar = tid >> 2, ac = (tid & 3) * 4;
    int br = tid >> 4, bc = (tid & 15) * 4;
    int rm = (tid >> 4) * 4, rn = (tid & 15) * 4;

    float acc[4][4];
#pragma unroll
    for (int i = 0; i < 4; ++i)
#pragma unroll
        for (int j = 0; j < 4; ++j) acc[i][j] = 0.0f;

    for (int k0 = 0; k0 < NDI; k0 += 16) {
        float4 a = *(const float4*)(A + (size_t)(bm + ar) * NDI + k0 + ac);
        As[ac+0][ar]=a.x; As[ac+1][ar]=a.y; As[ac+2][ar]=a.z; As[ac+3][ar]=a.w;
        *(float4*)(&Bs[br][bc]) =
            *(const float4*)(Bm + (size_t)(k0 + br) * ND + bn + bc);
        __syncthreads();
#pragma unroll
        for (int kk = 0; kk < 16; ++kk) {
            float4 av = *(const float4*)(&As[kk][rm]);
            float4 bv = *(const float4*)(&Bs[kk][rn]);
            acc[0][0]=fmaf(av.x,bv.x,acc[0][0]); acc[0][1]=fmaf(av.x,bv.y,acc[0][1]);
            acc[0][2]=fmaf(av.x,bv.z,acc[0][2]); acc[0][3]=fmaf(av.x,bv.w,acc[0][3]);
            acc[1][0]=fmaf(av.y,bv.x,acc[1][0]); acc[1][1]=fmaf(av.y,bv.y,acc[1][1]);
            acc[1][2]=fmaf(av.y,bv.z,acc[1][2]); acc[1][3]=fmaf(av.y,bv.w,acc[1][3]);
            acc[2][0]=fmaf(av.z,bv.x,acc[2][0]); acc[2][1]=fmaf(av.z,bv.y,acc[2][1]);
            acc[2][2]=fmaf(av.z,bv.z,acc[2][2]); acc[2][3]=fmaf(av.z,bv.w,acc[2][3]);
            acc[3][0]=fmaf(av.w,bv.x,acc[3][0]); acc[3][1]=fmaf(av.w,bv.y,acc[3][1]);
            acc[3][2]=fmaf(av.w,bv.z,acc[3][2]); acc[3][3]=fmaf(av.w,bv.w,acc[3][3]);
        }
        __syncthreads();
    }
    float4 bb;
    bb.x=bias[bn+rn+0]; bb.y=bias[bn+rn+1]; bb.z=bias[bn+rn+2]; bb.w=bias[bn+rn+3];
#pragma unroll
    for (int i = 0; i < 4; ++i) {
        float4 o;
        o.x=gelu_t(acc[i][0]+bb.x); o.y=gelu_t(acc[i][1]+bb.y);
        o.z=gelu_t(acc[i][2]+bb.z); o.w=gelu_t(acc[i][3]+bb.w);
        *(float4*)(g_f + (size_t)(bm+rm+i) * ND + bn + rn) = o;
    }
}

// =====================================================================
// Launch 2: mega — k/v GEMM [0,128) + meta [128,384) + qlast [384,392)
// =====================================================================
__global__ __launch_bounds__(256) void mega_kernel(
    const float* __restrict__ Wk, const float* __restrict__ Wv,
    const float* __restrict__ Wq,
    const float* __restrict__ Wm, const float* __restrict__ bm_)
{
    __shared__ float smem_u[2 * 16 * 64];
    int idx = blockIdx.x, tid = threadIdx.x;

    if (idx < 128) {
        float (*As)[64] = (float(*)[64])smem_u;
        float (*Bs)[64] = (float(*)[64])(smem_u + 16 * 64);
        const float* Bm = (idx >> 6) ? Wv : Wk;
        float* C = (idx >> 6) ? g_v : g_k;
        int bm = (idx & 31) * 64, bn = ((idx >> 5) & 1) * 64;
        int ar = tid >> 2, ac = (tid & 3) * 4;
        int br = tid >> 4, bc = (tid & 15) * 4;
        int rm = (tid >> 4) * 4, rn = (tid & 15) * 4;

        float acc[4][4];
#pragma unroll
        for (int i = 0; i < 4; ++i)
#pragma unroll
            for (int j = 0; j < 4; ++j) acc[i][j] = 0.0f;

        for (int k0 = 0; k0 < ND; k0 += 16) {
            float4 a = *(const float4*)(g_f + (size_t)(bm + ar) * ND + k0 + ac);
            As[ac+0][ar]=a.x; As[ac+1][ar]=a.y; As[ac+2][ar]=a.z; As[ac+3][ar]=a.w;
            *(float4*)(&Bs[br][bc]) =
                *(const float4*)(Bm + (size_t)(k0 + br) * ND + bn + bc);
            __syncthreads();
#pragma unroll
            for (int kk = 0; kk < 16; ++kk) {
                float4 av = *(const float4*)(&As[kk][rm]);
                float4 bv = *(const float4*)(&Bs[kk][rn]);
                acc[0][0]=fmaf(av.x,bv.x,acc[0][0]); acc[0][1]=fmaf(av.x,bv.y,acc[0][1]);
                acc[0][2]=fmaf(av.x,bv.z,acc[0][2]); acc[0][3]=fmaf(av.x,bv.w,acc[0][3]);
                acc[1][0]=fmaf(av.y,bv.x,acc[1][0]); acc[1][1]=fmaf(av.y,bv.y,acc[1][1]);
                acc[1][2]=fmaf(av.y,bv.z,acc[1][2]); acc[1][3]=fmaf(av.y,bv.w,acc[1][3]);
                acc[2][0]=fmaf(av.z,bv.x,acc[2][0]); acc[2][1]=fmaf(av.z,bv.y,acc[2][1]);
                acc[2][2]=fmaf(av.z,bv.z,acc[2][2]); acc[2][3]=fmaf(av.z,bv.w,acc[2][3]);
                acc[3][0]=fmaf(av.w,bv.x,acc[3][0]); acc[3][1]=fmaf(av.w,bv.y,acc[3][1]);
                acc[3][2]=fmaf(av.w,bv.z,acc[3][2]); acc[3][3]=fmaf(av.w,bv.w,acc[3][3]);
            }
            __syncthreads();
        }
#pragma unroll
        for (int i = 0; i < 4; ++i) {
            float4 o; o.x=acc[i][0]; o.y=acc[i][1]; o.z=acc[i][2]; o.w=acc[i][3];
            *(float4*)(C + (size_t)(bm+rm+i) * ND + bn + rn) = o;
        }
    } else if (idx < 384) {
        int warp = tid >> 5, lane = tid & 31;
        int row = (idx - 128) * 8 + warp;
        const float4* f4 = (const float4*)g_f + (size_t)row * 32;
        float4 fv = f4[lane];
        const float* wp = Wm + lane * 12;
        float d0 = fv.x*wp[0] + fv.y*wp[3] + fv.z*wp[6] + fv.w*wp[9];
        float d1 = fv.x*wp[1] + fv.y*wp[4] + fv.z*wp[7] + fv.w*wp[10];
        float d2 = fv.x*wp[2] + fv.y*wp[5] + fv.z*wp[8] + fv.w*wp[11];
#pragma unroll
        for (int o = 16; o > 0; o >>= 1) {
            d0 += __shfl_xor_sync(0xffffffffu, d0, o);
            d1 += __shfl_xor_sync(0xffffffffu, d1, o);
            d2 += __shfl_xor_sync(0xffffffffu, d2, o);
        }
        if (lane == 0) {
            g_theta[row] = 0.01f * sigmoid_f(d0 + bm_[0]);
            g_eta[row]   =         sigmoid_f(d1 + bm_[1]);
            g_alpha[row] = 0.1f  * sigmoid_f(d2 + bm_[2]);
        }
    } else {
        int b = idx - 384;
        float* fl = smem_u;
        float* part = smem_u + 128;
        if (tid < ND) fl[tid] = g_f[(size_t)(b * NT + NT - 1) * ND + tid];
        __syncthreads();
        int j = tid & 127, h = tid >> 7;
        float acc = 0.f;
        int i0 = h * 64;
#pragma unroll 16
        for (int i = 0; i < 64; ++i)
            acc = fmaf(fl[i0 + i], Wq[(size_t)(i0 + i) * ND + j], acc);
        part[tid] = acc;
        __syncthreads();
        if (tid < ND) g_qlast[b * ND + j] = part[tid] + part[tid + 128];
    }
}

// =====================================================================
// Launch 3: per batch — G = K K^T (16 tiles) + Gq (1 block); last CTA
// writes W row-major (R4 tail, coalesced both ways) + mcoef.
// =====================================================================
__global__ __launch_bounds__(256) void gprep_kernel()
{
    __shared__ float smem_u[2 * 16 * 64];
    __shared__ float eta_s[NT];
    __shared__ float r_s[NT];
    __shared__ float qsm[ND];
    __shared__ int sflag;

    int b = blockIdx.x / 17;
    int r = blockIdx.x % 17;
    int tid = threadIdx.x;
    const float* Kb = g_k + (size_t)b * NT * ND;
    float* Gb = g_G + (size_t)b * NT * NT;

    if (r < 16) {
        float (*As)[64] = (float(*)[64])smem_u;
        float (*Bs)[64] = (float(*)[64])(smem_u + 16 * 64);
        int I = (r >> 2) * 64, J = (r & 3) * 64;
        int ar = tid >> 2, ac = (tid & 3) * 4;
        int rm = (tid >> 4) * 4, rn = (tid & 15) * 4;

        float acc[4][4];
#pragma unroll
        for (int i = 0; i < 4; ++i)
#pragma unroll
            for (int j = 0; j < 4; ++j) acc[i][j] = 0.0f;

        for (int k0 = 0; k0 < ND; k0 += 16) {
            float4 a = *(const float4*)(Kb + (size_t)(I + ar) * ND + k0 + ac);
            As[ac+0][ar]=a.x; As[ac+1][ar]=a.y; As[ac+2][ar]=a.z; As[ac+3][ar]=a.w;
            float4 bvec = *(const float4*)(Kb + (size_t)(J + ar) * ND + k0 + ac);
            Bs[ac+0][ar]=bvec.x; Bs[ac+1][ar]=bvec.y; Bs[ac+2][ar]=bvec.z; Bs[ac+3][ar]=bvec.w;
            __syncthreads();
#pragma unroll
            for (int kk = 0; kk < 16; ++kk) {
                float4 av = *(const float4*)(&As[kk][rm]);
                float4 bv = *(const float4*)(&Bs[kk][rn]);
                acc[0][0]=fmaf(av.x,bv.x,acc[0][0]); acc[0][1]=fmaf(av.x,bv.y,acc[0][1]);
                acc[0][2]=fmaf(av.x,bv.z,acc[0][2]); acc[0][3]=fmaf(av.x,bv.w,acc[0][3]);
                acc[1][0]=fmaf(av.y,bv.x,acc[1][0]); acc[1][1]=fmaf(av.y,bv.y,acc[1][1]);
                acc[1][2]=fmaf(av.y,bv.z,acc[1][2]); acc[1][3]=fmaf(av.y,bv.w,acc[1][3]);
                acc[2][0]=fmaf(av.z,bv.x,acc[2][0]); acc[2][1]=fmaf(av.z,bv.y,acc[2][1]);
                acc[2][2]=fmaf(av.z,bv.z,acc[2][2]); acc[2][3]=fmaf(av.z,bv.w,acc[2][3]);
                acc[3][0]=fmaf(av.w,bv.x,acc[3][0]); acc[3][1]=fmaf(av.w,bv.y,acc[3][1]);
                acc[3][2]=fmaf(av.w,bv.z,acc[3][2]); acc[3][3]=fmaf(av.w,bv.w,acc[3][3]);
            }
            __syncthreads();
        }
#pragma unroll
        for (int i = 0; i < 4; ++i) {
            float4 o; o.x=acc[i][0]; o.y=acc[i][1]; o.z=acc[i][2]; o.w=acc[i][3];
            *(float4*)(Gb + (size_t)(I+rm+i) * NT + J + rn) = o;
        }
    } else {
        if (tid < ND) qsm[tid] = g_qlast[b * ND + tid];
        __syncthreads();
        const float* krow = Kb + (size_t)tid * ND;
        float acc = 0.f;
#pragma unroll 8
        for (int d = 0; d < ND; ++d) acc = fmaf(krow[d], qsm[d], acc);
        g_Gq[b * NT + tid] = acc;
    }

    __threadfence();
    __syncthreads();
    if (tid == 0) sflag = atomicAdd(&g_ctr[8 + b], 1);
    __syncthreads();
    if (sflag != 16) return;
    __threadfence();

    int tau = tid;
    eta_s[tid] = g_eta[b * NT + tid];
    r_s[tid]   = 1.0f - g_alpha[b * NT + tid];
    float th   = g_theta[b * NT + tau];
    float gq   = g_Gq[b * NT + tau];
    __syncthreads();

    float* Wb = g_W + (size_t)b * NT * NT;
    float h = 1.f, pp = 1.f;
    float gcur = Gb[NT + tau];
    for (int t = 1; t < NT; ++t) {
        float gnext = (t < NT-1) ? Gb[(size_t)(t+1) * NT + tau] : 0.f;
        if (tau < t) {
            Wb[(size_t)t * NT + tau] = -th * gcur * h;
            pp *= eta_s[t];
            h = fmaf(r_s[t], h, pp);
        } else {
            Wb[(size_t)t * NT + tau] = 0.f;   // defined upper part
        }
        gcur = gnext;
    }
    g_mcoef[b * NT + tau] = -th * h * gq;
}

// =====================================================================
// Launch 4: left-looking blocked triangular solve, E in smem.
// Grid = 8 batches x 8 col-blocks (16 cols) = 64 CTAs x 256 threads.
// =====================================================================
__device__ __forceinline__ void head_body(
    int b, int tid,
    const float* __restrict__ W_f, const float* __restrict__ b_f,
    const float* __restrict__ W1,  const float* __restrict__ b1,
    const float* __restrict__ g1,  const float* __restrict__ be1,
    const float* __restrict__ W2,  const float* __restrict__ b2,
    float* __restrict__ out,
    float* z, float* fused, float* tbuf, float* h)
{
    if (tid < ND)        z[tid] = g_f[(size_t)(b * NT + NT - 1) * ND + tid];
    else if (tid < 2*ND) z[tid] = g_mlast[b * ND + (tid - ND)];
    __syncthreads();
    if (tid < ND) {
        float acc = b_f[tid];
#pragma unroll 8
        for (int i = 0; i < 2 * ND; ++i)
            acc = fmaf(z[i], W_f[(size_t)i * ND + tid], acc);
        float g = sigmoid_f(acc);
        fused[tid] = z[tid] * g + z[ND + tid] * (1.0f - g);
    }
    __syncthreads();
    if (tid < ND) {
        float acc = b1[tid];
#pragma unroll 8
        for (int i = 0; i < ND; ++i)
            acc = fmaf(fused[i], W1[(size_t)i * ND + tid], acc);
        tbuf[tid] = acc;
    }
    __syncthreads();
    float sum = 0.f, sq = 0.f;
#pragma unroll 8
    for (int i = 0; i < ND; ++i) { float t = tbuf[i]; sum += t; sq += t*t; }
    float mu = sum * (1.0f / ND);
    float var = sq * (1.0f / ND) - mu * mu;
    float rstd = rsqrtf(var + 1e-5f);
    if (tid < ND) {
        float ln = (tbuf[tid] - mu) * rstd * g1[tid] + be1[tid];
        h[tid] = gelu_t(ln);
    }
    __syncthreads();
    for (int o = tid; o < NOUT; o += 256) {
        float acc = b2[o];
#pragma unroll 8
        for (int i = 0; i < ND; ++i)
            acc = fmaf(h[i], W2[(size_t)i * NOUT + o], acc);
        out[b * NOUT + o] = acc;
    }
}

__global__ __launch_bounds__(256, 1) void solve_head_kernel(
    const float* __restrict__ W_f, const float* __restrict__ b_f,
    const float* __restrict__ W1,  const float* __restrict__ b1,
    const float* __restrict__ g1,  const float* __restrict__ be1,
    const float* __restrict__ W2,  const float* __restrict__ b2,
    float* __restrict__ out)
{
    __shared__ __align__(16) float Es[NT * 20];   // E[t][c], 16 cols + pad
    __shared__ float Wst[32 * 33];                // GEMM W tile / reduce buf
    __shared__ float Wd[32 * 33];                 // diag block, transposed
    __shared__ float mco[NT];
    __shared__ float z[2 * ND];
    __shared__ float fusedv[ND];
    __shared__ float tbuf[ND];
    __shared__ float hh[ND];
    __shared__ int sflag;

    int tid = threadIdx.x;
    int b  = blockIdx.x >> 3;
    int cb = blockIdx.x & 7;
    const float* Wb = g_W + (size_t)b * NT * NT;

    // ---- E = -v for this column block (float4, coalesced) ----
    {
        const float* vb = g_v + (size_t)b * NT * ND + cb * 16;
#pragma unroll
        for (int rep = 0; rep < 4; ++rep) {
            int idx = rep * 256 + tid;        // 1024 float4 slots
            int t = idx >> 2, c4 = (idx & 3) * 4;
            float4 v4 = *(const float4*)(vb + (size_t)t * ND + c4);
            *(float4*)&Es[t * 20 + c4] = make_float4(-v4.x, -v4.y, -v4.z, -v4.w);
        }
    }
    mco[tid] = g_mcoef[b * NT + tid];
    __syncthreads();

    int gt = tid >> 3;            // 0..31 (t within chunk)
    int gh = (tid >> 2) & 1;      // k half
    int gq = tid & 3;             // col quad
    int lw = tid >> 5, lu = tid & 31;

    for (int C = 0; C < 8; ++C) {
        if (C > 0) {
            // ---- GEMM: E_C += W[32C.., 0..32C) @ E[0..32C) ----
            float4 acc = make_float4(0.f, 0.f, 0.f, 0.f);
            for (int kt = 0; kt < C; ++kt) {
                __syncthreads();
                {
                    float4 w4 = *(const float4*)(Wb +
                        (size_t)(32*C + (tid >> 3)) * NT + kt * 32 + (tid & 7) * 4);
                    int base = (tid >> 3) * 33 + (tid & 7) * 4;
                    Wst[base+0]=w4.x; Wst[base+1]=w4.y; Wst[base+2]=w4.z; Wst[base+3]=w4.w;
                }
                __syncthreads();
#pragma unroll
                for (int kk = 0; kk < 16; ++kk) {
                    float a = Wst[gt * 33 + gh * 16 + kk];
                    float4 e4 = *(const float4*)&Es[(kt*32 + gh*16 + kk) * 20 + gq * 4];
                    acc.x = fmaf(a, e4.x, acc.x);
                    acc.y = fmaf(a, e4.y, acc.y);
                    acc.z = fmaf(a, e4.z, acc.z);
                    acc.w = fmaf(a, e4.w, acc.w);
                }
            }
            // combine k-halves (h bit = tid bit 2)
            acc.x += __shfl_xor_sync(0xffffffffu, acc.x, 4);
            acc.y += __shfl_xor_sync(0xffffffffu, acc.y, 4);
            acc.z += __shfl_xor_sync(0xffffffffu, acc.z, 4);
            acc.w += __shfl_xor_sync(0xffffffffu, acc.w, 4);
            if (gh == 0) {
                float4* ep = (float4*)&Es[(32*C + gt) * 20 + gq * 4];
                float4 cur = *ep;
                cur.x += acc.x; cur.y += acc.y; cur.z += acc.z; cur.w += acc.w;
                *ep = cur;
            }
        }
        __syncthreads();

        // ---- stage diag block transposed: Wd[tt][u] = W[32C+u][32C+tt] ----
        {
            int u = tid >> 3, j = (tid & 7) * 4;
            float4 w4 = *(const float4*)(Wb + (size_t)(32*C + u) * NT + 32*C + j);
            Wd[(j+0)*33 + u] = w4.x;
            Wd[(j+1)*33 + u] = w4.y;
            Wd[(j+2)*33 + u] = w4.z;
            Wd[(j+3)*33 + u] = w4.w;
        }
        __syncthreads();

        // ---- warp-synchronous diag solve: warp = 2 cols, lane = slot ----
        {
            float e0 = Es[(32*C + lu) * 20 + 2*lw];
            float e1 = Es[(32*C + lu) * 20 + 2*lw + 1];
#pragma unroll 8
            for (int tt = 0; tt < 32; ++tt) {
                float wv = Wd[tt * 33 + lu];
                float b0 = __shfl_sync(0xffffffffu, e0, tt);
                float b1 = __shfl_sync(0xffffffffu, e1, tt);
                if (lu > tt) {
                    e0 = fmaf(wv, b0, e0);
                    e1 = fmaf(wv, b1, e1);
                }
            }
            Es[(32*C + lu) * 20 + 2*lw]     = e0;
            Es[(32*C + lu) * 20 + 2*lw + 1] = e1;
        }
        __syncthreads();
    }

    // ---- m_last for this column block ----
    {
        int c = tid & 15, part = tid >> 4;
        float s = 0.f;
#pragma unroll
        for (int r2 = 0; r2 < 16; ++r2)
            s = fmaf(mco[part*16 + r2], Es[(part*16 + r2) * 20 + c], s);
        Wst[part * 16 + c] = s;
    }
    __syncthreads();
    if (tid < 16) {
        float s = 0.f;
#pragma unroll
        for (int p = 0; p < 16; ++p) s += Wst[p * 16 + tid];
        g_mlast[b * ND + cb * 16 + tid] = s;
    }

    // ---- fused head on last CTA of batch ----
    __threadfence();
    __syncthreads();
    if (tid == 0) sflag = atomicAdd(&g_ctr[b], 1);
    __syncthreads();
    if (sflag == 7) {
        __threadfence();
        head_body(b, tid, W_f, b_f, W1, b1, g1, be1, W2, b2, out,
                  z, fusedv, tbuf, hh);
    }
}

// ---------------- launch ----------------------------------------------------
extern "C" void kernel_launch(void* const* d_in, const int* in_sizes, int n_in,
                              void* d_out, int out_size)
{
    const float* x   = (const float*)d_in[0];
    const float* W_b = (const float*)d_in[1];
    const float* b_b = (const float*)d_in[2];
    const float* Wk  = (const float*)d_in[3];
    const float* Wv  = (const float*)d_in[4];
    const float* Wq  = (const float*)d_in[5];
    const float* W_m = (const float*)d_in[6];
    const float* b_m = (const float*)d_in[7];
    const float* W_f = (const float*)d_in[8];
    const float* b_f = (const float*)d_in[9];
    const float* W1  = (const float*)d_in[10];
    const float* b1  = (const float*)d_in[11];
    const float* g1  = (const float*)d_in[12];
    const float* be1 = (const float*)d_in[13];
    const float* W2  = (const float*)d_in[14];
    const float* b2  = (const float*)d_in[15];
    float* out = (float*)d_out;

    fgemm_kernel<<<dim3(32, 2), 256>>>(x, W_b, b_b);
    mega_kernel<<<392, 256>>>(Wk, Wv, Wq, W_m, b_m);
    gprep_kernel<<<NB * 17, 256>>>();
    solve_head_kernel<<<64, 256>>>(W_f, b_f, W1, b1, g1, be1, W2, b2, out);
}